// round 9
// baseline (speedup 1.0000x reference)
#include <cuda_runtime.h>
#include <cstdint>

// Scratch (no cudaMalloc allowed)
static __device__ float g_act  [8ull * 1024 * 2048];   // activated intermediate (tf32-rounded)
static __device__ float g_dispr[8ull * 1024 * 2048];   // dispatched, tf32-rounded

// ---------------- PTX helpers ----------------
__device__ __forceinline__ uint32_t s2u(const void* p) {
    uint32_t a;
    asm("{ .reg .u64 t; cvta.to.shared.u64 t, %1; cvt.u32.u64 %0, t; }" : "=r"(a) : "l"(p));
    return a;
}
__device__ __forceinline__ uint32_t tf32cvt(float x) {
    uint32_t r; asm("cvt.rna.tf32.f32 %0, %1;" : "=r"(r) : "f"(x)); return r;
}
__device__ __forceinline__ float tf32f(float x) {
    float r; asm("cvt.rna.tf32.f32 %0, %1;" : "=f"(r) : "f"(x)); return r;
}
#define CP_ASYNC16(dst, src) \
    asm volatile("cp.async.cg.shared.global [%0], [%1], 16;" :: "r"(dst), "l"(src))
#define CP_COMMIT() asm volatile("cp.async.commit_group;")
#define CP_WAIT(n)  asm volatile("cp.async.wait_group %0;" :: "n"(n))

__device__ __forceinline__ void mma_tf32(float c[4], uint32_t a0, uint32_t a1, uint32_t a2,
                                         uint32_t a3, uint32_t b0, uint32_t b1) {
    asm("mma.sync.aligned.m16n8k8.row.col.f32.tf32.tf32.f32 "
        "{%0,%1,%2,%3}, {%4,%5,%6,%7}, {%8,%9}, {%0,%1,%2,%3};"
        : "+f"(c[0]), "+f"(c[1]), "+f"(c[2]), "+f"(c[3])
        : "r"(a0), "r"(a1), "r"(a2), "r"(a3), "r"(b0), "r"(b1));
}

// ---------------- prologue: tf32-round copy ----------------
__global__ void round_copy_k(const float* __restrict__ in, float* __restrict__ out, size_t n4) {
    size_t i = (size_t)blockIdx.x * blockDim.x + threadIdx.x;
    size_t stride = (size_t)gridDim.x * blockDim.x;
    for (; i < n4; i += stride) {
        float4 v = ((const float4*)in)[i];
        v.x = tf32f(v.x); v.y = tf32f(v.y); v.z = tf32f(v.z); v.w = tf32f(v.w);
        ((float4*)out)[i] = v;
    }
}

// ---------------- main GEMM ----------------
// C[128,256] per CTA, 8 warps as 2(M) x 4(N) of 64x64 warp tiles, BK=32, 3-stage cp.async.
// A (g_dispr / g_act) is pre-rounded tf32 -> raw-bit LDS.64 frag loads with the
// k-permutation: instruction slot c <-> global k 2c, slot c+4 <-> 2c+1 (consistent in B).
// B (weights, fp32) cvt'd in-register with the same permutation.
// EPI 0: gu = A@B + bias -> clipped GLU -> g_act.   EPI 1: out = A@B + bias.
template <int EPI>
__global__ void __launch_bounds__(256, 1)
moe_mma_sync(const float* __restrict__ Aall,
             const float* __restrict__ Ball,
             const float* __restrict__ biasAll,
             float* __restrict__ outAll,
             int M, int N, int K)
{
    constexpr int BM = 128, BN = 256, BK = 32, STG = 3;
    constexpr int AST = 40;    // A smem row stride (floats); LDS.64 frag loads conflict-free
    constexpr int BST = 260;   // B smem row stride (floats); permuted-row reads conflict-free
    constexpr int A_ST = BM * AST;   // 5120 floats / stage
    constexpr int B_ST = BK * BST;   // 8320 floats / stage

    extern __shared__ float smem[];
    float* As = smem;
    float* Bs = smem + STG * A_ST;
    const uint32_t as_u = s2u(As);
    const uint32_t bs_u = s2u(Bs);

    const int tid  = threadIdx.x;
    const int lane = tid & 31;
    const int warp = tid >> 5;      // 0..7
    const int wm = warp & 1;        // M half (0..1)
    const int wn = warp >> 1;       // N quarter (0..3)
    const int r = lane >> 2;        // 0..7
    const int c = lane & 3;         // 0..3

    const int e  = blockIdx.z;
    const int mB = blockIdx.y * BM;
    const int nB = blockIdx.x * BN;

    const float* A = Aall + (size_t)e * M * K;
    const float* B = Ball + (size_t)e * K * N;
    const float* bias = biasAll + (size_t)e * N;

    const float* Asrc0 = A + (size_t)mB * K;
    const float* Bsrc0 = B + nB;
    const int KIT = K / BK;

    auto load_stage = [&](int s, int kt) {
        const float* Asrc = Asrc0 + kt * BK;
        const float* Bsrc = Bsrc0 + (size_t)(kt * BK) * N;
        const uint32_t a_b = as_u + (uint32_t)s * A_ST * 4;
        const uint32_t b_b = bs_u + (uint32_t)s * B_ST * 4;
        // A: 128 rows x 8 chunks (16B) = 1024 chunks; 4 per thread
#pragma unroll
        for (int i = 0; i < 4; i++) {
            int idx = tid + i * 256;
            int ar = idx >> 3, ac = idx & 7;
            CP_ASYNC16(a_b + (uint32_t)(ar * AST + ac * 4) * 4, Asrc + (size_t)ar * K + ac * 4);
        }
        // B: 32 rows x 64 chunks (16B) = 2048 chunks; 8 per thread
#pragma unroll
        for (int i = 0; i < 8; i++) {
            int idx = tid + i * 256;
            int br = idx >> 6, bc = idx & 63;
            CP_ASYNC16(b_b + (uint32_t)(br * BST + bc * 4) * 4, Bsrc + (size_t)br * N + bc * 4);
        }
    };

    float acc[4][8][4];
#pragma unroll
    for (int mi = 0; mi < 4; mi++)
#pragma unroll
        for (int ni = 0; ni < 8; ni++)
#pragma unroll
            for (int q = 0; q < 4; q++) acc[mi][ni][q] = 0.f;

#pragma unroll
    for (int s = 0; s < STG - 1; s++) { load_stage(s, s); CP_COMMIT(); }

    for (int kt = 0; kt < KIT; kt++) {
        CP_WAIT(STG - 2);
        __syncthreads();
        if (kt + STG - 1 < KIT) load_stage((kt + STG - 1) % STG, kt + STG - 1);
        CP_COMMIT();

        const float* Ab = As + (kt % STG) * A_ST;
        const float* Bb = Bs + (kt % STG) * B_ST;
#pragma unroll
        for (int ks = 0; ks < BK / 8; ks++) {
            // A fragments (64 rows): raw tf32 bits via LDS.64.
            uint32_t af[4][4];
#pragma unroll
            for (int mi = 0; mi < 4; mi++) {
                int row = wm * 64 + mi * 16 + r;
                float2 lo = *(const float2*)&Ab[row * AST + ks * 8 + 2 * c];
                float2 hi = *(const float2*)&Ab[(row + 8) * AST + ks * 8 + 2 * c];
                af[mi][0] = __float_as_uint(lo.x);
                af[mi][1] = __float_as_uint(hi.x);
                af[mi][2] = __float_as_uint(lo.y);
                af[mi][3] = __float_as_uint(hi.y);
            }
            // B fragments (64 cols): cvt in-register, same k-permutation.
            uint32_t bf[8][2];
#pragma unroll
            for (int ni = 0; ni < 8; ni++) {
                int col = wn * 64 + ni * 8 + r;
                bf[ni][0] = tf32cvt(Bb[(ks * 8 + 2 * c) * BST + col]);
                bf[ni][1] = tf32cvt(Bb[(ks * 8 + 2 * c + 1) * BST + col]);
            }
#pragma unroll
            for (int mi = 0; mi < 4; mi++)
#pragma unroll
                for (int ni = 0; ni < 8; ni++)
                    mma_tf32(acc[mi][ni], af[mi][0], af[mi][1], af[mi][2], af[mi][3],
                             bf[ni][0], bf[ni][1]);
        }
    }

    // ---------------- epilogue ----------------
    if (EPI == 0) {
        const int halfN = N >> 1;   // 2048
        float* act = g_act + (size_t)e * M * halfN;
#pragma unroll
        for (int mi = 0; mi < 4; mi++) {
            const int m = mB + wm * 64 + mi * 16 + r;
#pragma unroll
            for (int ni = 0; ni < 8; ni++) {
                const int gucol = nB + wn * 64 + ni * 8 + 2 * c;
                const float bg = __ldg(&bias[gucol]);
                const float bu = __ldg(&bias[gucol + 1]);
#pragma unroll
                for (int h = 0; h < 2; h++) {
                    float g = acc[mi][ni][2 * h]     + bg;
                    float u = acc[mi][ni][2 * h + 1] + bu;
                    g = fminf(g, 7.0f);
                    u = fminf(fmaxf(u, -7.0f), 7.0f);
                    float glu = g / (1.0f + __expf(-1.702f * g));
                    act[(size_t)(m + 8 * h) * halfN + (gucol >> 1)] = tf32f((u + 1.0f) * glu);
                }
            }
        }
    } else {
        float* out = outAll + (size_t)e * M * N;
#pragma unroll
        for (int mi = 0; mi < 4; mi++) {
            const int m = mB + wm * 64 + mi * 16 + r;
#pragma unroll
            for (int ni = 0; ni < 8; ni++) {
                const int col = nB + wn * 64 + ni * 8 + 2 * c;
                const float b0 = __ldg(&bias[col]);
                const float b1 = __ldg(&bias[col + 1]);
                float2 v0 = make_float2(acc[mi][ni][0] + b0, acc[mi][ni][1] + b1);
                float2 v1 = make_float2(acc[mi][ni][2] + b0, acc[mi][ni][3] + b1);
                *(float2*)&out[(size_t)m * N + col]       = v0;
                *(float2*)&out[(size_t)(m + 8) * N + col] = v1;
            }
        }
    }
}

// ---------------- host ----------------
extern "C" void kernel_launch(void* const* d_in, const int* in_sizes, int n_in,
                              void* d_out, int out_size)
{
    const float* disp = (const float*)d_in[0];  // (1,1,8,1024,2048)
    const float* w1   = (const float*)d_in[1];  // (8,2048,4096)
    const float* b1   = (const float*)d_in[2];  // (8,4096)
    const float* w2   = (const float*)d_in[3];  // (8,2048,2048)
    const float* b2   = (const float*)d_in[4];  // (8,2048)
    float* out = (float*)d_out;                 // (8,1,1024,2048) fp32

    const int M = 1024, H = 2048, I2 = 4096, I = 2048;

    void *p_act, *p_dispr;
    cudaGetSymbolAddress(&p_act, g_act);
    cudaGetSymbolAddress(&p_dispr, g_dispr);

    constexpr int STG = 3;
    const int smem_bytes = STG * (128 * 40 + 32 * 260) * 4;   // 161,280 B (1 CTA/SM)
    cudaFuncSetAttribute(moe_mma_sync<0>, cudaFuncAttributeMaxDynamicSharedMemorySize, smem_bytes);
    cudaFuncSetAttribute(moe_mma_sync<1>, cudaFuncAttributeMaxDynamicSharedMemorySize, smem_bytes);

    // Prologue: tf32-round dispatched (A of GEMM1); g_act is written pre-rounded by GEMM1.
    round_copy_k<<<2048, 256>>>(disp, (float*)p_dispr, (size_t)8 * 1024 * 2048 / 4);

    // GEMM1: gu = disp_r @ w1 (+b1) -> GLU -> g_act
    moe_mma_sync<0><<<dim3(I2 / 256, M / 128, 8), 256, smem_bytes>>>(
        (const float*)p_dispr, w1, b1, nullptr, M, I2, H);
    // GEMM2: out = g_act @ w2 (+b2)
    moe_mma_sync<1><<<dim3(H / 256, M / 128, 8), 256, smem_bytes>>>(
        (const float*)p_act, w2, b2, out, M, H, I);
}

// round 14
// speedup vs baseline: 1.2448x; 1.2448x over previous
#include <cuda_runtime.h>
#include <cstdint>

// Scratch (no cudaMalloc allowed)
static __device__ float g_act  [8ull * 1024 * 2048];   // activated intermediate (tf32-rounded)
static __device__ float g_dispr[8ull * 1024 * 2048];   // dispatched, tf32-rounded

// ---------------- PTX helpers ----------------
__device__ __forceinline__ uint32_t s2u(const void* p) {
    uint32_t a;
    asm("{ .reg .u64 t; cvta.to.shared.u64 t, %1; cvt.u32.u64 %0, t; }" : "=r"(a) : "l"(p));
    return a;
}
__device__ __forceinline__ uint32_t tf32cvt(float x) {
    uint32_t r; asm("cvt.rna.tf32.f32 %0, %1;" : "=r"(r) : "f"(x)); return r;
}
__device__ __forceinline__ float tf32f(float x) {
    float r; asm("cvt.rna.tf32.f32 %0, %1;" : "=f"(r) : "f"(x)); return r;
}
#define CP_ASYNC16(dst, src) \
    asm volatile("cp.async.cg.shared.global [%0], [%1], 16;" :: "r"(dst), "l"(src))
#define CP_COMMIT() asm volatile("cp.async.commit_group;")
#define CP_WAIT(n)  asm volatile("cp.async.wait_group %0;" :: "n"(n))

__device__ __forceinline__ void mma_tf32(float c[4], uint32_t a0, uint32_t a1, uint32_t a2,
                                         uint32_t a3, uint32_t b0, uint32_t b1) {
    asm("mma.sync.aligned.m16n8k8.row.col.f32.tf32.tf32.f32 "
        "{%0,%1,%2,%3}, {%4,%5,%6,%7}, {%8,%9}, {%0,%1,%2,%3};"
        : "+f"(c[0]), "+f"(c[1]), "+f"(c[2]), "+f"(c[3])
        : "r"(a0), "r"(a1), "r"(a2), "r"(a3), "r"(b0), "r"(b1));
}

// ---------------- prologue: tf32-round copy ----------------
__global__ void round_copy_k(const float* __restrict__ in, float* __restrict__ out, size_t n4) {
    size_t i = (size_t)blockIdx.x * blockDim.x + threadIdx.x;
    size_t stride = (size_t)gridDim.x * blockDim.x;
    for (; i < n4; i += stride) {
        float4 v = ((const float4*)in)[i];
        v.x = tf32f(v.x); v.y = tf32f(v.y); v.z = tf32f(v.z); v.w = tf32f(v.w);
        ((float4*)out)[i] = v;
    }
}

// ---------------- main GEMM ----------------
// C[128,128] per CTA, 4 warps as 2(M) x 2(N) of 64x64 warp tiles, BK=32, 3-stage cp.async.
// Explicit register double-buffering of fragments + LATE stage barrier: the
// CP_WAIT/__syncthreads for the next k-tile happens after 3 of 4 ks-blocks, and the
// next tile's first fragments are loaded under the last MMA block, so HMMA issue
// never goes idle at tile boundaries.
// A (g_dispr / g_act) is pre-rounded tf32 -> raw-bit LDS.64 frag loads with the
// k-permutation: instruction slot c <-> global k 2c, slot c+4 <-> 2c+1 (consistent in B).
// EPI 0: gu = A@B + bias -> clipped GLU -> g_act.   EPI 1: out = A@B + bias.
template <int EPI>
__global__ void __launch_bounds__(128, 2)
moe_mma_sync(const float* __restrict__ Aall,
             const float* __restrict__ Ball,
             const float* __restrict__ biasAll,
             float* __restrict__ outAll,
             int M, int N, int K)
{
    constexpr int BM = 128, BN = 128, BK = 32, STG = 3;
    constexpr int AST = 40;    // A smem row stride (floats); LDS.64 frag loads conflict-free
    constexpr int BST = 132;   // B smem row stride (floats); permuted-row reads conflict-free
    constexpr int A_ST = BM * AST;
    constexpr int B_ST = BK * BST;

    extern __shared__ float smem[];
    float* As = smem;
    float* Bs = smem + STG * A_ST;
    const uint32_t as_u = s2u(As);
    const uint32_t bs_u = s2u(Bs);

    const int tid  = threadIdx.x;
    const int lane = tid & 31;
    const int warp = tid >> 5;      // 0..3
    const int wm = warp & 1;        // M half
    const int wn = warp >> 1;       // N half
    const int r = lane >> 2;        // 0..7
    const int c = lane & 3;         // 0..3

    const int e  = blockIdx.z;
    const int mB = blockIdx.y * BM;
    const int nB = blockIdx.x * BN;

    const float* A = Aall + (size_t)e * M * K;
    const float* B = Ball + (size_t)e * K * N;
    const float* bias = biasAll + (size_t)e * N;

    const float* Asrc0 = A + (size_t)mB * K;
    const float* Bsrc0 = B + nB;
    const int KIT = K / BK;   // 64

    auto load_stage = [&](int s, int kt) {
        const float* Asrc = Asrc0 + kt * BK;
        const float* Bsrc = Bsrc0 + (size_t)(kt * BK) * N;
        const uint32_t a_b = as_u + (uint32_t)s * A_ST * 4;
        const uint32_t b_b = bs_u + (uint32_t)s * B_ST * 4;
#pragma unroll
        for (int i = 0; i < 8; i++) {
            int idx = tid + i * 128;
            int ar = idx >> 3, ac = idx & 7;          // A: 128 rows x 8 chunks
            CP_ASYNC16(a_b + (uint32_t)(ar * AST + ac * 4) * 4, Asrc + (size_t)ar * K + ac * 4);
            int br = idx >> 5, bc = idx & 31;         // B: 32 rows x 32 chunks
            CP_ASYNC16(b_b + (uint32_t)(br * BST + bc * 4) * 4, Bsrc + (size_t)br * N + bc * 4);
        }
    };

    // fragment loaders (register double-buffered by caller)
    auto load_afrag = [&](const float* Ab, int ks, uint32_t af[4][4]) {
#pragma unroll
        for (int mi = 0; mi < 4; mi++) {
            int row = wm * 64 + mi * 16 + r;
            float2 lo = *(const float2*)&Ab[row * AST + ks * 8 + 2 * c];
            float2 hi = *(const float2*)&Ab[(row + 8) * AST + ks * 8 + 2 * c];
            af[mi][0] = __float_as_uint(lo.x);
            af[mi][1] = __float_as_uint(hi.x);
            af[mi][2] = __float_as_uint(lo.y);
            af[mi][3] = __float_as_uint(hi.y);
        }
    };
    auto load_bfrag = [&](const float* Bb, int ks, uint32_t bf[8][2]) {
#pragma unroll
        for (int ni = 0; ni < 8; ni++) {
            int col = wn * 64 + ni * 8 + r;
            bf[ni][0] = tf32cvt(Bb[(ks * 8 + 2 * c) * BST + col]);
            bf[ni][1] = tf32cvt(Bb[(ks * 8 + 2 * c + 1) * BST + col]);
        }
    };

    float acc[4][8][4];
#pragma unroll
    for (int mi = 0; mi < 4; mi++)
#pragma unroll
        for (int ni = 0; ni < 8; ni++)
#pragma unroll
            for (int q = 0; q < 4; q++) acc[mi][ni][q] = 0.f;

    // prologue: issue stages 0 and 1; wait for stage 0; preload its ks=0 frags
    load_stage(0, 0); CP_COMMIT();
    load_stage(1, 1); CP_COMMIT();
    CP_WAIT(1);
    __syncthreads();

    uint32_t afb[2][4][4];
    uint32_t bfb[2][8][2];
    load_afrag(As, 0, afb[0]);
    load_bfrag(Bs, 0, bfb[0]);

    for (int kt = 0; kt < KIT; kt++) {
        const float* Ab = As + (kt % STG) * A_ST;
        const float* Bb = Bs + (kt % STG) * B_ST;
#pragma unroll
        for (int ks = 0; ks < 4; ks++) {
            const int cur = ks & 1, nxt = cur ^ 1;
            if (ks < 3) {
                // prefetch next ks of current tile under this MMA block
                load_afrag(Ab, ks + 1, afb[nxt]);
                load_bfrag(Bb, ks + 1, bfb[nxt]);
            } else if (kt + 1 < KIT) {
                // late barrier: next stage long since requested; drain + sync,
                // then preload next tile's ks=0 frags and issue the stage after.
                CP_WAIT(0);
                __syncthreads();
                const float* Abn = As + ((kt + 1) % STG) * A_ST;
                const float* Bbn = Bs + ((kt + 1) % STG) * B_ST;
                load_afrag(Abn, 0, afb[nxt]);
                load_bfrag(Bbn, 0, bfb[nxt]);
                if (kt + 2 < KIT) load_stage((kt + 2) % STG, kt + 2);
                CP_COMMIT();
            }
#pragma unroll
            for (int mi = 0; mi < 4; mi++)
#pragma unroll
                for (int ni = 0; ni < 8; ni++)
                    mma_tf32(acc[mi][ni],
                             afb[cur][mi][0], afb[cur][mi][1], afb[cur][mi][2], afb[cur][mi][3],
                             bfb[cur][ni][0], bfb[cur][ni][1]);
        }
    }

    // ---------------- epilogue ----------------
    if (EPI == 0) {
        const int halfN = N >> 1;   // 2048
        float* act = g_act + (size_t)e * M * halfN;
#pragma unroll
        for (int mi = 0; mi < 4; mi++) {
            const int m = mB + wm * 64 + mi * 16 + r;
#pragma unroll
            for (int ni = 0; ni < 8; ni++) {
                const int gucol = nB + wn * 64 + ni * 8 + 2 * c;
                const float bg = __ldg(&bias[gucol]);
                const float bu = __ldg(&bias[gucol + 1]);
#pragma unroll
                for (int h = 0; h < 2; h++) {
                    float g = acc[mi][ni][2 * h]     + bg;
                    float u = acc[mi][ni][2 * h + 1] + bu;
                    g = fminf(g, 7.0f);
                    u = fminf(fmaxf(u, -7.0f), 7.0f);
                    float glu = g / (1.0f + __expf(-1.702f * g));
                    act[(size_t)(m + 8 * h) * halfN + (gucol >> 1)] = tf32f((u + 1.0f) * glu);
                }
            }
        }
    } else {
        float* out = outAll + (size_t)e * M * N;
#pragma unroll
        for (int mi = 0; mi < 4; mi++) {
            const int m = mB + wm * 64 + mi * 16 + r;
#pragma unroll
            for (int ni = 0; ni < 8; ni++) {
                const int col = nB + wn * 64 + ni * 8 + 2 * c;
                const float b0 = __ldg(&bias[col]);
                const float b1 = __ldg(&bias[col + 1]);
                float2 v0 = make_float2(acc[mi][ni][0] + b0, acc[mi][ni][1] + b1);
                float2 v1 = make_float2(acc[mi][ni][2] + b0, acc[mi][ni][3] + b1);
                *(float2*)&out[(size_t)m * N + col]       = v0;
                *(float2*)&out[(size_t)(m + 8) * N + col] = v1;
            }
        }
    }
}

// ---------------- host ----------------
extern "C" void kernel_launch(void* const* d_in, const int* in_sizes, int n_in,
                              void* d_out, int out_size)
{
    const float* disp = (const float*)d_in[0];  // (1,1,8,1024,2048)
    const float* w1   = (const float*)d_in[1];  // (8,2048,4096)
    const float* b1   = (const float*)d_in[2];  // (8,4096)
    const float* w2   = (const float*)d_in[3];  // (8,2048,2048)
    const float* b2   = (const float*)d_in[4];  // (8,2048)
    float* out = (float*)d_out;                 // (8,1,1024,2048) fp32

    const int M = 1024, H = 2048, I2 = 4096, I = 2048;

    void *p_act, *p_dispr;
    cudaGetSymbolAddress(&p_act, g_act);
    cudaGetSymbolAddress(&p_dispr, g_dispr);

    constexpr int STG = 3;
    const int smem_bytes = STG * (128 * 40 + 32 * 132) * 4;   // 112,128 B (2 CTAs/SM)
    cudaFuncSetAttribute(moe_mma_sync<0>, cudaFuncAttributeMaxDynamicSharedMemorySize, smem_bytes);
    cudaFuncSetAttribute(moe_mma_sync<1>, cudaFuncAttributeMaxDynamicSharedMemorySize, smem_bytes);

    // Prologue: tf32-round dispatched (A of GEMM1); g_act is written pre-rounded by GEMM1.
    round_copy_k<<<2048, 256>>>(disp, (float*)p_dispr, (size_t)8 * 1024 * 2048 / 4);

    // GEMM1: gu = disp_r @ w1 (+b1) -> GLU -> g_act
    moe_mma_sync<0><<<dim3(I2 / 128, M / 128, 8), 128, smem_bytes>>>(
        (const float*)p_dispr, w1, b1, nullptr, M, I2, H);
    // GEMM2: out = g_act @ w2 (+b2)
    moe_mma_sync<1><<<dim3(H / 128, M / 128, 8), 128, smem_bytes>>>(
        (const float*)p_act, w2, b2, out, M, H, I);
}